// round 2
// baseline (speedup 1.0000x reference)
#include <cuda_runtime.h>
#include <math.h>

#define NNODES 8192
#define KNBR   32

// ---------------- scratch (static device arrays; no allocation) ----------------
__device__ float g_proj [NNODES * 1152];      // q(192) | kv(384) | qp_raw(144) | kvp_raw(432)
__device__ float g_wcat [384 * 1152];
__device__ float g_bcat [1152];
__device__ float g_qpts [NNODES * 144];       // (H,PQ,3) transformed
__device__ float g_kvpts[NNODES * 432];       // (H,12,3) transformed
__device__ float g_bpair[NNODES * KNBR * 12]; // sqrt(1/3)*(z@w_b+b_b)
__device__ float g_pairz[NNODES * KNBR * 32]; // z@w_dz+b_dz
__device__ float g_cat  [NNODES * 960];

// ---------------- weight packing ----------------
__global__ void pack_weights(const float* __restrict__ wq, const float* __restrict__ bq,
                             const float* __restrict__ wkv, const float* __restrict__ bkv,
                             const float* __restrict__ wqp, const float* __restrict__ bqp,
                             const float* __restrict__ wkvp, const float* __restrict__ bkvp)
{
    int t = blockIdx.x * blockDim.x + threadIdx.x;
    int stride = gridDim.x * blockDim.x;
    for (int i = t; i < 384 * 1152; i += stride) {
        int r = i / 1152, c = i % 1152;
        float v;
        if      (c < 192) v = wq  [r * 192 + c];
        else if (c < 576) v = wkv [r * 384 + (c - 192)];
        else if (c < 720) v = wqp [r * 144 + (c - 576)];
        else              v = wkvp[r * 432 + (c - 720)];
        g_wcat[i] = v;
    }
    if (t < 1152) {
        int c = t; float v;
        if      (c < 192) v = bq [c];
        else if (c < 576) v = bkv[c - 192];
        else if (c < 720) v = bqp[c - 576];
        else              v = bkvp[c - 720];
        g_bcat[c] = v;
    }
}

// ---------------- classic fp32 SGEMM: C[M,N] = A[M,K]@B[K,N] + bias ----------------
// 128x128 block tile, BK=8, 256 threads, 8x8 per-thread microtile.
template<int N, int K>
__device__ __forceinline__ void gemm_body(const float* __restrict__ A,
                                          const float* __restrict__ B,
                                          const float* __restrict__ bias,
                                          float* __restrict__ C)
{
    __shared__ float As[8][132];   // padded to dodge store conflicts
    __shared__ float Bs[8][128];
    const int tid  = threadIdx.x;
    const int brow = blockIdx.y * 128;
    const int bcol = blockIdx.x * 128;
    const int arow = tid >> 1, acol = (tid & 1) * 4;
    const int bkr  = tid >> 5, bco  = (tid & 31) * 4;
    const int ty = tid >> 4, tx = tid & 15;

    float acc[8][8];
#pragma unroll
    for (int i = 0; i < 8; i++)
#pragma unroll
        for (int j = 0; j < 8; j++) acc[i][j] = 0.f;

    for (int k0 = 0; k0 < K; k0 += 8) {
        float4 av = *(const float4*)(A + (size_t)(brow + arow) * K + k0 + acol);
        As[acol + 0][arow] = av.x;
        As[acol + 1][arow] = av.y;
        As[acol + 2][arow] = av.z;
        As[acol + 3][arow] = av.w;
        *(float4*)&Bs[bkr][bco] = *(const float4*)(B + (size_t)(k0 + bkr) * N + bcol + bco);
        __syncthreads();
#pragma unroll
        for (int kk = 0; kk < 8; kk++) {
            float ar[8], br[8];
#pragma unroll
            for (int i = 0; i < 8; i++) ar[i] = As[kk][ty * 8 + i];
#pragma unroll
            for (int j = 0; j < 8; j++) br[j] = Bs[kk][tx * 8 + j];
#pragma unroll
            for (int i = 0; i < 8; i++)
#pragma unroll
                for (int j = 0; j < 8; j++) acc[i][j] = fmaf(ar[i], br[j], acc[i][j]);
        }
        __syncthreads();
    }
#pragma unroll
    for (int i = 0; i < 8; i++) {
        int r = brow + ty * 8 + i;
#pragma unroll
        for (int j = 0; j < 8; j++) {
            int c = bcol + tx * 8 + j;
            C[(size_t)r * N + c] = acc[i][j] + bias[c];
        }
    }
}

__global__ __launch_bounds__(256) void gemm_proj(const float* __restrict__ s)
{
    gemm_body<1152, 384>(s, g_wcat, g_bcat, g_proj);
}
__global__ __launch_bounds__(256) void gemm_out(const float* __restrict__ wout,
                                                const float* __restrict__ bout,
                                                float* __restrict__ out)
{
    gemm_body<384, 960>(g_cat, wout, bout, out);
}

// ---------------- rigid transform of qp/kvp points ----------------
__global__ __launch_bounds__(192) void transform_points(const float* __restrict__ rot,
                                                        const float* __restrict__ trans)
{
    int n = blockIdx.x;
    __shared__ float R[9], T[3];
    int t = threadIdx.x;
    if (t < 9) R[t] = rot[n * 9 + t];
    if (t < 3) T[t] = trans[n * 3 + t];
    __syncthreads();
    if (t < 48) {
        // qp: flat layout (3,48): coord i of point j at [i*48 + j]
        const float* base = g_proj + (size_t)n * 1152 + 576;
        float x = base[t], y = base[48 + t], z = base[96 + t];
        float* o = g_qpts + (size_t)n * 144 + t * 3;
        o[0] = fmaf(R[0], x, fmaf(R[1], y, fmaf(R[2], z, T[0])));
        o[1] = fmaf(R[3], x, fmaf(R[4], y, fmaf(R[5], z, T[1])));
        o[2] = fmaf(R[6], x, fmaf(R[7], y, fmaf(R[8], z, T[2])));
    } else {
        int j = t - 48;  // 0..143, (3,144) layout
        const float* base = g_proj + (size_t)n * 1152 + 720;
        float x = base[j], y = base[144 + j], z = base[288 + j];
        float* o = g_kvpts + (size_t)n * 432 + j * 3;
        o[0] = fmaf(R[0], x, fmaf(R[1], y, fmaf(R[2], z, T[0])));
        o[1] = fmaf(R[3], x, fmaf(R[4], y, fmaf(R[5], z, T[1])));
        o[2] = fmaf(R[6], x, fmaf(R[7], y, fmaf(R[8], z, T[2])));
    }
}

// ---------------- fused z projections: b_pair (H=12) + pair_z (32) ----------------
// one block = 32 edges; 384 threads as (48 cols x 8 row-groups); each thread 4 rows.
__global__ __launch_bounds__(384) void zproj(const float* __restrict__ z,
                                             const float* __restrict__ wb,  const float* __restrict__ bb,
                                             const float* __restrict__ wdz, const float* __restrict__ bdz)
{
    __shared__ float sw[128 * 48];   // padded col stride 48
    __shared__ float sz[32 * 128];
    int tid = threadIdx.x;
    for (int i = tid; i < 128 * 44; i += 384) {
        int k = i / 44, c = i % 44;
        sw[k * 48 + c] = (c < 12) ? wb[k * 12 + c] : wdz[k * 32 + (c - 12)];
    }
    size_t e0 = (size_t)blockIdx.x * 32;
    const float* zb = z + e0 * 128;
    for (int i = tid; i < 32 * 128; i += 384) sz[i] = zb[i];
    __syncthreads();

    int c = tid % 48, ty = tid / 48;  // ty in [0,8)
    if (c < 44) {
        float a0 = 0.f, a1 = 0.f, a2 = 0.f, a3 = 0.f;
#pragma unroll 8
        for (int k = 0; k < 128; k++) {
            float w = sw[k * 48 + c];
            a0 = fmaf(w, sz[(ty     ) * 128 + k], a0);
            a1 = fmaf(w, sz[(ty +  8) * 128 + k], a1);
            a2 = fmaf(w, sz[(ty + 16) * 128 + k], a2);
            a3 = fmaf(w, sz[(ty + 24) * 128 + k], a3);
        }
        if (c < 12) {
            float b = bb[c];
            const float S = 0.5773502691896258f;  // sqrt(1/3)
            g_bpair[(e0 + ty     ) * 12 + c] = S * (a0 + b);
            g_bpair[(e0 + ty +  8) * 12 + c] = S * (a1 + b);
            g_bpair[(e0 + ty + 16) * 12 + c] = S * (a2 + b);
            g_bpair[(e0 + ty + 24) * 12 + c] = S * (a3 + b);
        } else {
            int cc = c - 12; float b = bdz[cc];
            g_pairz[(e0 + ty     ) * 32 + cc] = a0 + b;
            g_pairz[(e0 + ty +  8) * 32 + cc] = a1 + b;
            g_pairz[(e0 + ty + 16) * 32 + cc] = a2 + b;
            g_pairz[(e0 + ty + 24) * 32 + cc] = a3 + b;
        }
    }
}

// ---------------- fused attention: logits + softmax + o / o_pt / o_pair ----------------
__global__ __launch_bounds__(384) void attn_kernel(const int* __restrict__ edge_index,
                                                   const float* __restrict__ rot,
                                                   const float* __restrict__ trans,
                                                   const float* __restrict__ mask,
                                                   const float* __restrict__ head_weights)
{
    int n = blockIdx.x;
    int t = threadIdx.x;
    __shared__ int   s_idx[32];
    __shared__ float s_mask[32];
    __shared__ float s_q[192];
    __shared__ float s_qp[144];
    __shared__ float s_R[9], s_T[3];
    __shared__ float s_hw[12];
    __shared__ float s_a[12][33];
    __shared__ float s_opt[288];
    __shared__ float s_pz[32][33];

    if (t < 32) {
        int nb = edge_index[n * 32 + t];
        s_idx[t]  = nb;
        s_mask[t] = mask[nb];
    }
    if (t >= 32 && t < 224)  s_q [t - 32]  = g_proj[(size_t)n * 1152 + (t - 32)];
    if (t >= 224 && t < 368) s_qp[t - 224] = g_qpts[(size_t)n * 144 + (t - 224)];
    if (t >= 368 && t < 377) s_R [t - 368] = rot  [n * 9 + (t - 368)];
    if (t >= 377 && t < 380) s_T [t - 377] = trans[n * 3 + (t - 377)];
    if (t < 12) {
        float x = head_weights[t];
        float sp = (x > 20.f) ? x : log1pf(expf(x));
        s_hw[t] = sp * 0.13608276348795434f;   // softplus * sqrt(1/54)
    }
    __syncthreads();

    // --- logits + softmax: warp w handles head w ---
    {
        int h = t >> 5, k = t & 31;
        int nb = s_idx[k];
        const float* kg = g_proj + (size_t)nb * 1152 + 192 + h * 32;  // k part of kv
        float dot = 0.f;
#pragma unroll
        for (int c = 0; c < 16; c++) dot = fmaf(s_q[h * 16 + c], kg[c], dot);
        const float* kp = g_kvpts + (size_t)nb * 432 + h * 36;        // k_pts: first 12 floats
        float pt = 0.f;
#pragma unroll
        for (int pi = 0; pi < 12; pi++) {
            float d = s_qp[h * 12 + pi] - kp[pi];
            pt = fmaf(d, d, pt);
        }
        float logit = dot * 0.14433756729740643f          // sqrt(1/48)
                    + g_bpair[((size_t)n * 32 + k) * 12 + h]
                    - 0.5f * s_hw[h] * pt
                    + 100000.0f * (s_mask[k] - 1.0f);
        float m = logit;
#pragma unroll
        for (int o = 16; o; o >>= 1) m = fmaxf(m, __shfl_xor_sync(0xffffffffu, m, o));
        float e = expf(logit - m);
        float ssum = e;
#pragma unroll
        for (int o = 16; o; o >>= 1) ssum += __shfl_xor_sync(0xffffffffu, ssum, o);
        s_a[h][k] = e / ssum;
    }
    // stage pair_z tile (h-independent)
    for (int i = t; i < 32 * 32; i += 384)
        s_pz[i >> 5][i & 31] = g_pairz[((size_t)n * 32 + (i >> 5)) * 32 + (i & 31)];
    __syncthreads();

    float* catn = g_cat + (size_t)n * 960;

    // o: scalar part, 192 outputs
    if (t < 192) {
        int h = t >> 4, c = t & 15;
        float acc = 0.f;
#pragma unroll 4
        for (int k = 0; k < 32; k++)
            acc = fmaf(s_a[h][k], g_proj[(size_t)s_idx[k] * 1152 + 192 + h * 32 + 16 + c], acc);
        catn[h * 16 + c] = acc;
    }
    // o_pt global accumulation: 288 outputs
    if (t < 288) {
        int j = t / 3, i = t - j * 3;  // j = h*8+p
        int h = j >> 3, p = j & 7;
        float acc = 0.f;
#pragma unroll 4
        for (int k = 0; k < 32; k++)
            acc = fmaf(s_a[h][k], g_kvpts[(size_t)s_idx[k] * 432 + h * 36 + (4 + p) * 3 + i], acc);
        s_opt[t] = acc;
    }
    // o_pair: 384 outputs (all threads)
    {
        int h = t >> 5, c = t & 31;
        float acc = 0.f;
#pragma unroll
        for (int k = 0; k < 32; k++)
            acc = fmaf(s_a[h][k], s_pz[k][c], acc);
        catn[576 + h * 32 + c] = acc;
    }
    __syncthreads();
    // inverse rigid transform + norm: 96 points
    if (t < 96) {
        float gx = s_opt[t * 3 + 0] - s_T[0];
        float gy = s_opt[t * 3 + 1] - s_T[1];
        float gz = s_opt[t * 3 + 2] - s_T[2];
        float lx = fmaf(s_R[0], gx, fmaf(s_R[3], gy, s_R[6] * gz));
        float ly = fmaf(s_R[1], gx, fmaf(s_R[4], gy, s_R[7] * gz));
        float lz = fmaf(s_R[2], gx, fmaf(s_R[5], gy, s_R[8] * gz));
        catn[192 + t] = lx;
        catn[288 + t] = ly;
        catn[384 + t] = lz;
        catn[480 + t] = sqrtf(fmaf(lx, lx, fmaf(ly, ly, fmaf(lz, lz, 1e-8f))));
    }
}

// ---------------- launch ----------------
extern "C" void kernel_launch(void* const* d_in, const int* in_sizes, int n_in,
                              void* d_out, int out_size)
{
    const float* s     = (const float*)d_in[0];
    const float* z     = (const float*)d_in[1];
    const int*   ei    = (const int*)  d_in[2];
    const float* rot   = (const float*)d_in[3];
    const float* trans = (const float*)d_in[4];
    const float* mask  = (const float*)d_in[5];
    const float* w_q   = (const float*)d_in[6];
    const float* b_q   = (const float*)d_in[7];
    const float* w_kv  = (const float*)d_in[8];
    const float* b_kv  = (const float*)d_in[9];
    const float* w_qp  = (const float*)d_in[10];
    const float* b_qp  = (const float*)d_in[11];
    const float* w_kvp = (const float*)d_in[12];
    const float* b_kvp = (const float*)d_in[13];
    const float* w_b   = (const float*)d_in[14];
    const float* b_b   = (const float*)d_in[15];
    const float* w_dz  = (const float*)d_in[16];
    const float* b_dz  = (const float*)d_in[17];
    const float* hw    = (const float*)d_in[18];
    const float* w_out = (const float*)d_in[19];
    const float* b_out = (const float*)d_in[20];
    float* out = (float*)d_out;

    pack_weights<<<256, 256>>>(w_q, b_q, w_kv, b_kv, w_qp, b_qp, w_kvp, b_kvp);
    gemm_proj<<<dim3(1152 / 128, NNODES / 128), 256>>>(s);
    transform_points<<<NNODES, 192>>>(rot, trans);
    zproj<<<NNODES, 384>>>(z, w_b, b_b, w_dz, b_dz);
    attn_kernel<<<NNODES, 384>>>(ei, rot, trans, mask, hw);
    gemm_out<<<dim3(384 / 128, NNODES / 128), 256>>>(w_out, b_out, out);
}

// round 5
// speedup vs baseline: 1.0451x; 1.0451x over previous
#include <cuda_runtime.h>
#include <math.h>

#define NNODES 8192
#define KNBR   32

// ---------------- scratch (static device arrays; no allocation) ----------------
__device__ float g_proj [NNODES * 1152];      // q(192) | kv(384) | qp_raw(144) | kvp_raw(432)
__device__ float g_wcat [384 * 1152];
__device__ float g_bcat [1152];
__device__ float g_qpts [NNODES * 144];       // (H,PQ,3) transformed
__device__ float g_kvpts[NNODES * 432];       // (H,12,3) transformed
__device__ float g_bpair[NNODES * KNBR * 12]; // sqrt(1/3)*(z@w_b+b_b)
__device__ float g_pairz[NNODES * KNBR * 32]; // z@w_dz+b_dz
__device__ float g_cat  [NNODES * 960];

// ---------------- weight packing ----------------
__global__ void pack_weights(const float* __restrict__ wq, const float* __restrict__ bq,
                             const float* __restrict__ wkv, const float* __restrict__ bkv,
                             const float* __restrict__ wqp, const float* __restrict__ bqp,
                             const float* __restrict__ wkvp, const float* __restrict__ bkvp)
{
    int t = blockIdx.x * blockDim.x + threadIdx.x;
    int stride = gridDim.x * blockDim.x;
    for (int i = t; i < 384 * 1152; i += stride) {
        int r = i / 1152, c = i % 1152;
        float v;
        if      (c < 192) v = wq  [r * 192 + c];
        else if (c < 576) v = wkv [r * 384 + (c - 192)];
        else if (c < 720) v = wqp [r * 144 + (c - 576)];
        else              v = wkvp[r * 432 + (c - 720)];
        g_wcat[i] = v;
    }
    if (t < 1152) {
        int c = t; float v;
        if      (c < 192) v = bq [c];
        else if (c < 576) v = bkv[c - 192];
        else if (c < 720) v = bqp[c - 576];
        else              v = bkvp[c - 720];
        g_bcat[c] = v;
    }
}

// ---------------- fp32 SGEMM, double-buffered: C[M,N] = A[M,K]@B[K,N] + bias ----------------
// 128x128 block tile, BK=8, 256 threads, 8x8 per-thread microtile, 2-stage smem pipeline.
template<int N, int K>
__device__ __forceinline__ void gemm_body(const float* __restrict__ A,
                                          const float* __restrict__ B,
                                          const float* __restrict__ bias,
                                          float* __restrict__ C)
{
    __shared__ float As[2][8][132];   // padded to dodge store conflicts
    __shared__ float Bs[2][8][128];
    const int tid  = threadIdx.x;
    const int brow = blockIdx.y * 128;
    const int bcol = blockIdx.x * 128;
    const int arow = tid >> 1, acol = (tid & 1) * 4;
    const int bkr  = tid >> 5, bco  = (tid & 31) * 4;
    const int ty = tid >> 4, tx = tid & 15;

    float acc[8][8];
#pragma unroll
    for (int i = 0; i < 8; i++)
#pragma unroll
        for (int j = 0; j < 8; j++) acc[i][j] = 0.f;

    // prologue: stage k0 = 0 into buffer 0
    {
        float4 av = *(const float4*)(A + (size_t)(brow + arow) * K + acol);
        As[0][acol + 0][arow] = av.x;
        As[0][acol + 1][arow] = av.y;
        As[0][acol + 2][arow] = av.z;
        As[0][acol + 3][arow] = av.w;
        *(float4*)&Bs[0][bkr][bco] = *(const float4*)(B + (size_t)bkr * N + bcol + bco);
    }
    __syncthreads();

    int buf = 0;
    for (int k0 = 0; k0 < K; k0 += 8) {
        const bool more = (k0 + 8) < K;
        float4 av2, bv2;
        if (more) {
            av2 = *(const float4*)(A + (size_t)(brow + arow) * K + (k0 + 8) + acol);
            bv2 = *(const float4*)(B + (size_t)(k0 + 8 + bkr) * N + bcol + bco);
        }
#pragma unroll
        for (int kk = 0; kk < 8; kk++) {
            float ar[8], br[8];
#pragma unroll
            for (int i = 0; i < 8; i++) ar[i] = As[buf][kk][ty * 8 + i];
#pragma unroll
            for (int j = 0; j < 8; j++) br[j] = Bs[buf][kk][tx * 8 + j];
#pragma unroll
            for (int i = 0; i < 8; i++)
#pragma unroll
                for (int j = 0; j < 8; j++) acc[i][j] = fmaf(ar[i], br[j], acc[i][j]);
        }
        if (more) {
            As[buf ^ 1][acol + 0][arow] = av2.x;
            As[buf ^ 1][acol + 1][arow] = av2.y;
            As[buf ^ 1][acol + 2][arow] = av2.z;
            As[buf ^ 1][acol + 3][arow] = av2.w;
            *(float4*)&Bs[buf ^ 1][bkr][bco] = bv2;
            __syncthreads();
            buf ^= 1;
        }
    }
#pragma unroll
    for (int i = 0; i < 8; i++) {
        int r = brow + ty * 8 + i;
#pragma unroll
        for (int j = 0; j < 8; j++) {
            int c = bcol + tx * 8 + j;
            C[(size_t)r * N + c] = acc[i][j] + bias[c];
        }
    }
}

__global__ __launch_bounds__(256) void gemm_proj(const float* __restrict__ s)
{
    gemm_body<1152, 384>(s, g_wcat, g_bcat, g_proj);
}
__global__ __launch_bounds__(256) void gemm_out(const float* __restrict__ wout,
                                                const float* __restrict__ bout,
                                                float* __restrict__ out)
{
    gemm_body<384, 960>(g_cat, wout, bout, out);
}

// ---------------- rigid transform of qp/kvp points ----------------
__global__ __launch_bounds__(192) void transform_points(const float* __restrict__ rot,
                                                        const float* __restrict__ trans)
{
    int n = blockIdx.x;
    __shared__ float R[9], T[3];
    int t = threadIdx.x;
    if (t < 9) R[t] = rot[n * 9 + t];
    if (t < 3) T[t] = trans[n * 3 + t];
    __syncthreads();
    if (t < 48) {
        // qp: flat layout (3,48): coord i of point j at [i*48 + j]
        const float* base = g_proj + (size_t)n * 1152 + 576;
        float x = base[t], y = base[48 + t], z = base[96 + t];
        float* o = g_qpts + (size_t)n * 144 + t * 3;
        o[0] = fmaf(R[0], x, fmaf(R[1], y, fmaf(R[2], z, T[0])));
        o[1] = fmaf(R[3], x, fmaf(R[4], y, fmaf(R[5], z, T[1])));
        o[2] = fmaf(R[6], x, fmaf(R[7], y, fmaf(R[8], z, T[2])));
    } else {
        int j = t - 48;  // 0..143, (3,144) layout
        const float* base = g_proj + (size_t)n * 1152 + 720;
        float x = base[j], y = base[144 + j], z = base[288 + j];
        float* o = g_kvpts + (size_t)n * 432 + j * 3;
        o[0] = fmaf(R[0], x, fmaf(R[1], y, fmaf(R[2], z, T[0])));
        o[1] = fmaf(R[3], x, fmaf(R[4], y, fmaf(R[5], z, T[1])));
        o[2] = fmaf(R[6], x, fmaf(R[7], y, fmaf(R[8], z, T[2])));
    }
}

// ---------------- fused z projections: b_pair (H=12) + pair_z (32) ----------------
// Row-per-thread: block = 256 threads = 256 EDGES (grid = total_edges/256 = 1024!).
// 44 fp32 accumulators per thread. K=128 split into 4 passes of 32;
// z value via conflict-free scalar LDS (row stride 33), weights via broadcast LDS.128.
__global__ __launch_bounds__(256) void zproj(const float* __restrict__ z,
                                             const float* __restrict__ wb,  const float* __restrict__ bb,
                                             const float* __restrict__ wdz, const float* __restrict__ bdz)
{
    __shared__ float sz[256 * 33];   // 256 rows, stride 33 -> bank = (row + k) % 32
    __shared__ float sw[32 * 44];    // k-major weight chunk, 44 floats/row (16B aligned)
    const int tid = threadIdx.x;
    const size_t e0 = (size_t)blockIdx.x * 256;

    float acc[44];
#pragma unroll
    for (int c = 0; c < 44; c++) acc[c] = 0.f;

    for (int pass = 0; pass < 4; pass++) {
        if (pass) __syncthreads();   // smem reuse guard
        // stage z chunk: 256 rows x 32 k (coalesced: 32 consecutive floats per warp)
#pragma unroll
        for (int idx = tid; idx < 256 * 32; idx += 256) {
            int row = idx >> 5, k = idx & 31;
            sz[row * 33 + k] = z[(e0 + row) * 128 + pass * 32 + k];
        }
        // stage weight chunk: 32 k x 44 c
        for (int i = tid; i < 32 * 44; i += 256) {
            int kk = i / 44, c = i % 44;
            sw[kk * 44 + c] = (c < 12) ? wb[(pass * 32 + kk) * 12 + c]
                                       : wdz[(pass * 32 + kk) * 32 + (c - 12)];
        }
        __syncthreads();

        const float4* sw4 = (const float4*)sw;
#pragma unroll 4
        for (int k = 0; k < 32; k++) {
            float zv = sz[tid * 33 + k];
#pragma unroll
            for (int j = 0; j < 11; j++) {
                float4 w = sw4[k * 11 + j];
                acc[4 * j + 0] = fmaf(zv, w.x, acc[4 * j + 0]);
                acc[4 * j + 1] = fmaf(zv, w.y, acc[4 * j + 1]);
                acc[4 * j + 2] = fmaf(zv, w.z, acc[4 * j + 2]);
                acc[4 * j + 3] = fmaf(zv, w.w, acc[4 * j + 3]);
            }
        }
    }

    // epilogue: bias, scale, vectorized stores
    const size_t e = e0 + tid;
    const float S = 0.5773502691896258f;  // sqrt(1/3)
    float tb[12];
#pragma unroll
    for (int c = 0; c < 12; c++) tb[c] = S * (acc[c] + __ldg(bb + c));
    float4* pb = (float4*)(g_bpair + e * 12);
#pragma unroll
    for (int i = 0; i < 3; i++)
        pb[i] = make_float4(tb[4 * i], tb[4 * i + 1], tb[4 * i + 2], tb[4 * i + 3]);
    float tz[32];
#pragma unroll
    for (int c = 0; c < 32; c++) tz[c] = acc[12 + c] + __ldg(bdz + c);
    float4* pz = (float4*)(g_pairz + e * 32);
#pragma unroll
    for (int i = 0; i < 8; i++)
        pz[i] = make_float4(tz[4 * i], tz[4 * i + 1], tz[4 * i + 2], tz[4 * i + 3]);
}

// ---------------- fused attention: logits + softmax + o / o_pt / o_pair ----------------
__global__ __launch_bounds__(384) void attn_kernel(const int* __restrict__ edge_index,
                                                   const float* __restrict__ rot,
                                                   const float* __restrict__ trans,
                                                   const float* __restrict__ mask,
                                                   const float* __restrict__ head_weights)
{
    int n = blockIdx.x;
    int t = threadIdx.x;
    __shared__ int   s_idx[32];
    __shared__ float s_mask[32];
    __shared__ float s_q[192];
    __shared__ float s_qp[144];
    __shared__ float s_R[9], s_T[3];
    __shared__ float s_hw[12];
    __shared__ float s_a[12][33];
    __shared__ float s_opt[288];
    __shared__ float s_pz[32][33];

    if (t < 32) {
        int nb = edge_index[n * 32 + t];
        s_idx[t]  = nb;
        s_mask[t] = mask[nb];
    }
    if (t >= 32 && t < 224)  s_q [t - 32]  = g_proj[(size_t)n * 1152 + (t - 32)];
    if (t >= 224 && t < 368) s_qp[t - 224] = g_qpts[(size_t)n * 144 + (t - 224)];
    if (t >= 368 && t < 377) s_R [t - 368] = rot  [n * 9 + (t - 368)];
    if (t >= 377 && t < 380) s_T [t - 377] = trans[n * 3 + (t - 377)];
    if (t < 12) {
        float x = head_weights[t];
        float sp = (x > 20.f) ? x : log1pf(expf(x));
        s_hw[t] = sp * 0.13608276348795434f;   // softplus * sqrt(1/54)
    }
    __syncthreads();

    // --- logits + softmax: warp w handles head w ---
    {
        int h = t >> 5, k = t & 31;
        int nb = s_idx[k];
        const float* kg = g_proj + (size_t)nb * 1152 + 192 + h * 32;  // k part of kv
        float dot = 0.f;
#pragma unroll
        for (int c = 0; c < 16; c++) dot = fmaf(s_q[h * 16 + c], kg[c], dot);
        const float* kp = g_kvpts + (size_t)nb * 432 + h * 36;        // k_pts: first 12 floats
        float pt = 0.f;
#pragma unroll
        for (int pi = 0; pi < 12; pi++) {
            float d = s_qp[h * 12 + pi] - kp[pi];
            pt = fmaf(d, d, pt);
        }
        float logit = dot * 0.14433756729740643f          // sqrt(1/48)
                    + g_bpair[((size_t)n * 32 + k) * 12 + h]
                    - 0.5f * s_hw[h] * pt
                    + 100000.0f * (s_mask[k] - 1.0f);
        float m = logit;
#pragma unroll
        for (int o = 16; o; o >>= 1) m = fmaxf(m, __shfl_xor_sync(0xffffffffu, m, o));
        float e = expf(logit - m);
        float ssum = e;
#pragma unroll
        for (int o = 16; o; o >>= 1) ssum += __shfl_xor_sync(0xffffffffu, ssum, o);
        s_a[h][k] = e / ssum;
    }
    // stage pair_z tile (h-independent)
    for (int i = t; i < 32 * 32; i += 384)
        s_pz[i >> 5][i & 31] = g_pairz[((size_t)n * 32 + (i >> 5)) * 32 + (i & 31)];
    __syncthreads();

    float* catn = g_cat + (size_t)n * 960;

    // o: scalar part, 192 outputs
    if (t < 192) {
        int h = t >> 4, c = t & 15;
        float acc = 0.f;
#pragma unroll 4
        for (int k = 0; k < 32; k++)
            acc = fmaf(s_a[h][k], g_proj[(size_t)s_idx[k] * 1152 + 192 + h * 32 + 16 + c], acc);
        catn[h * 16 + c] = acc;
    }
    // o_pt global accumulation: 288 outputs
    if (t < 288) {
        int j = t / 3, i = t - j * 3;  // j = h*8+p
        int h = j >> 3, p = j & 7;
        float acc = 0.f;
#pragma unroll 4
        for (int k = 0; k < 32; k++)
            acc = fmaf(s_a[h][k], g_kvpts[(size_t)s_idx[k] * 432 + h * 36 + (4 + p) * 3 + i], acc);
        s_opt[t] = acc;
    }
    // o_pair: 384 outputs (all threads)
    {
        int h = t >> 5, c = t & 31;
        float acc = 0.f;
#pragma unroll
        for (int k = 0; k < 32; k++)
            acc = fmaf(s_a[h][k], s_pz[k][c], acc);
        catn[576 + h * 32 + c] = acc;
    }
    __syncthreads();
    // inverse rigid transform + norm: 96 points
    if (t < 96) {
        float gx = s_opt[t * 3 + 0] - s_T[0];
        float gy = s_opt[t * 3 + 1] - s_T[1];
        float gz = s_opt[t * 3 + 2] - s_T[2];
        float lx = fmaf(s_R[0], gx, fmaf(s_R[3], gy, s_R[6] * gz));
        float ly = fmaf(s_R[1], gx, fmaf(s_R[4], gy, s_R[7] * gz));
        float lz = fmaf(s_R[2], gx, fmaf(s_R[5], gy, s_R[8] * gz));
        catn[192 + t] = lx;
        catn[288 + t] = ly;
        catn[384 + t] = lz;
        catn[480 + t] = sqrtf(fmaf(lx, lx, fmaf(ly, ly, fmaf(lz, lz, 1e-8f))));
    }
}

// ---------------- launch ----------------
extern "C" void kernel_launch(void* const* d_in, const int* in_sizes, int n_in,
                              void* d_out, int out_size)
{
    const float* s     = (const float*)d_in[0];
    const float* z     = (const float*)d_in[1];
    const int*   ei    = (const int*)  d_in[2];
    const float* rot   = (const float*)d_in[3];
    const float* trans = (const float*)d_in[4];
    const float* mask  = (const float*)d_in[5];
    const float* w_q   = (const float*)d_in[6];
    const float* b_q   = (const float*)d_in[7];
    const float* w_kv  = (const float*)d_in[8];
    const float* b_kv  = (const float*)d_in[9];
    const float* w_qp  = (const float*)d_in[10];
    const float* b_qp  = (const float*)d_in[11];
    const float* w_kvp = (const float*)d_in[12];
    const float* b_kvp = (const float*)d_in[13];
    const float* w_b   = (const float*)d_in[14];
    const float* b_b   = (const float*)d_in[15];
    const float* w_dz  = (const float*)d_in[16];
    const float* b_dz  = (const float*)d_in[17];
    const float* hw    = (const float*)d_in[18];
    const float* w_out = (const float*)d_in[19];
    const float* b_out = (const float*)d_in[20];
    float* out = (float*)d_out;

    pack_weights<<<256, 256>>>(w_q, b_q, w_kv, b_kv, w_qp, b_qp, w_kvp, b_kvp);
    gemm_proj<<<dim3(1152 / 128, NNODES / 128), 256>>>(s);
    transform_points<<<NNODES, 192>>>(rot, trans);
    zproj<<<(NNODES * KNBR) / 256, 256>>>(z, w_b, b_b, w_dz, b_dz);   // 1024 blocks: ALL edges
    attn_kernel<<<NNODES, 384>>>(ei, rot, trans, mask, hw);
    gemm_out<<<dim3(384 / 128, NNODES / 128), 256>>>(w_out, b_out, out);
}